// round 10
// baseline (speedup 1.0000x reference)
#include <cuda_runtime.h>
#include <cuda_fp16.h>

#define D_MODEL 32
#define SEQ 128

static __device__ __forceinline__ __half2 h2ex2(__half2 a) {
    unsigned int ua = *reinterpret_cast<unsigned int*>(&a);
    unsigned int ur;
    asm("ex2.approx.f16x2 %0, %1;" : "=r"(ur) : "r"(ua));
    return *reinterpret_cast<__half2*>(&ur);
}

__global__ __launch_bounds__(SEQ) void attn_fused_kernel(
    const float* __restrict__ x,
    const float* __restrict__ Wt, const float* __restrict__ bt,
    const float* __restrict__ Wq, const float* __restrict__ bq,
    const float* __restrict__ Wk,
    const float* __restrict__ Wv, const float* __restrict__ bv,
    const float* __restrict__ Wo, const float* __restrict__ bo,
    float* __restrict__ out)
{
    __shared__ unsigned int sd_p[SEQ / 2];  // half2 pairs of d+ = x - mx  (<= 0)
    __shared__ unsigned int sd_m[SEQ / 2];  // half2 pairs of d- = x - mn  (>= 0)
    __shared__ float smx[4], smn[4], ssum[4];
    __shared__ float sparams[4];

    const int b = blockIdx.x;
    const int t = threadIdx.x;
    const int w = t >> 5, l = t & 31;

    const float xv = x[(size_t)b * SEQ + t];

    // block max/min of x (softmax stabilization, fp32)
    float mx = xv, mn = xv;
#pragma unroll
    for (int o = 16; o > 0; o >>= 1) {
        mx = fmaxf(mx, __shfl_xor_sync(0xffffffffu, mx, o));
        mn = fminf(mn, __shfl_xor_sync(0xffffffffu, mn, o));
    }
    if (l == 0) { smx[w] = mx; smn[w] = mn; }

    // warp 0: collapse all weights into 4 scalars (L2-resident loads)
    if (w == 0) {
        float qa = 0.f, qb = 0.f, ka = 0.f, va = 0.f, vb = 0.f;
#pragma unroll
        for (int d = 0; d < D_MODEL; d++) {
            float wt  = __ldg(&Wt[d]);
            float btd = __ldg(&bt[d]);
            float wq  = __ldg(&Wq[d * D_MODEL + l]);
            float wk  = __ldg(&Wk[d * D_MODEL + l]);
            float wv  = __ldg(&Wv[d * D_MODEL + l]);
            qa = fmaf(wt,  wq, qa);
            qb = fmaf(btd, wq, qb);
            ka = fmaf(wt,  wk, ka);
            va = fmaf(wt,  wv, va);
            vb = fmaf(btd, wv, vb);
        }
        qb += __ldg(&bq[l]);
        vb += __ldg(&bv[l]);
        float wo = __ldg(&Wo[l]);

        float A  = qa * ka;
        float C  = qb * ka;
        float al = va * wo;
        float be = vb * wo;
#pragma unroll
        for (int o = 16; o > 0; o >>= 1) {
            A  += __shfl_xor_sync(0xffffffffu, A,  o);
            C  += __shfl_xor_sync(0xffffffffu, C,  o);
            al += __shfl_xor_sync(0xffffffffu, al, o);
            be += __shfl_xor_sync(0xffffffffu, be, o);
        }
        if (l == 0) {
            const float L2E = 1.4426950408889634f;
            float inv = L2E / sqrtf((float)D_MODEL);  // fold 1/sqrt(D) and log2(e)
            sparams[0] = A * inv;
            sparams[1] = C * inv;
            sparams[2] = al;
            sparams[3] = be + __ldg(&bo[0]);
        }
    }
    __syncthreads();

    mx = fmaxf(fmaxf(smx[0], smx[1]), fmaxf(smx[2], smx[3]));
    mn = fminf(fminf(smn[0], smn[1]), fminf(smn[2], smn[3]));

    // fp32-exact offsets, rounded once to fp16; pair (even,odd) via shfl
    {
        float dp = xv - mx;                 // <= 0, == 0 for the max element
        float dm = xv - mn;                 // >= 0
        float dpn = __shfl_xor_sync(0xffffffffu, dp, 1);
        float dmn = __shfl_xor_sync(0xffffffffu, dm, 1);
        if ((t & 1) == 0) {
            __half2 hp = __floats2half2_rn(dp, dpn);
            __half2 hm = __floats2half2_rn(dm, dmn);
            sd_p[t >> 1] = *reinterpret_cast<unsigned int*>(&hp);
            sd_m[t >> 1] = *reinterpret_cast<unsigned int*>(&hm);
        }
    }
    __syncthreads();

    const float u = fmaf(sparams[0], xv, sparams[1]);  // log2-domain logit slope
    const bool  pos = (u >= 0.f);
    const float xstar = pos ? mx : mn;                 // argmax logit anchor
    const uint4* sd4 = reinterpret_cast<const uint4*>(pos ? sd_p : sd_m);
    const __half2 u2 = __half2half2(__float2half_rn(u));

    float num_f = 0.f, den_f = 0.f;
#pragma unroll 1
    for (int blk = 0; blk < 4; blk++) {                // 32 elems per chunk
        __half2 nA = __float2half2_rn(0.f), nB = __float2half2_rn(0.f);
        __half2 dA = __float2half2_rn(0.f), dB = __float2half2_rn(0.f);
#pragma unroll
        for (int j = 0; j < 4; j++) {                  // 8 elems per iter
            uint4 q = sd4[blk * 4 + j];
            __half2 d0 = *reinterpret_cast<__half2*>(&q.x);
            __half2 d1 = *reinterpret_cast<__half2*>(&q.y);
            __half2 d2 = *reinterpret_cast<__half2*>(&q.z);
            __half2 d3 = *reinterpret_cast<__half2*>(&q.w);
            __half2 e0 = h2ex2(__hmul2(u2, d0));       // z = u*d <= 0
            __half2 e1 = h2ex2(__hmul2(u2, d1));
            __half2 e2 = h2ex2(__hmul2(u2, d2));
            __half2 e3 = h2ex2(__hmul2(u2, d3));
            nA = __hfma2(e0, d0, nA);  dA = __hadd2(dA, e0);
            nB = __hfma2(e1, d1, nB);  dB = __hadd2(dB, e1);
            nA = __hfma2(e2, d2, nA);  dA = __hadd2(dA, e2);
            nB = __hfma2(e3, d3, nB);  dB = __hadd2(dB, e3);
        }
        float2 dsum = __half22float2(__hadd2(dA, dB));
        float2 nsum = __half22float2(__hadd2(nA, nB));
        den_f += dsum.x + dsum.y;
        num_f += nsum.x + nsum.y;
    }

    // m = softmax-weighted mean of x = x* + (sum e*d)/(sum e)
    float m = fmaf(__fdividef(num_f, den_f), 1.0f, xstar);

#pragma unroll
    for (int o = 16; o > 0; o >>= 1)
        m += __shfl_xor_sync(0xffffffffu, m, o);
    if (l == 0) ssum[w] = m;
    __syncthreads();
    if (t == 0) {
        float s = (ssum[0] + ssum[1] + ssum[2] + ssum[3]) * (1.0f / (float)SEQ);
        out[b] = fmaf(sparams[2], s, sparams[3]);
    }
}

extern "C" void kernel_launch(void* const* d_in, const int* in_sizes, int n_in,
                              void* d_out, int out_size) {
    const float* x  = (const float*)d_in[0];
    const float* Wt = (const float*)d_in[1];
    const float* bt = (const float*)d_in[2];
    const float* Wq = (const float*)d_in[3];
    const float* bq = (const float*)d_in[4];
    const float* Wk = (const float*)d_in[5];
    const float* Wv = (const float*)d_in[7];
    const float* bv = (const float*)d_in[8];
    const float* Wo = (const float*)d_in[9];
    const float* bo = (const float*)d_in[10];
    float* out = (float*)d_out;

    const int B = in_sizes[0] / SEQ;

    attn_fused_kernel<<<B, SEQ>>>(x, Wt, bt, Wq, bq, Wk, Wv, bv, Wo, bo, out);
}

// round 13
// speedup vs baseline: 1.3008x; 1.3008x over previous
#include <cuda_runtime.h>
#include <cuda_fp16.h>

#define D_MODEL 32
#define SEQ 128

// {A*log2e/sqrt(D), C*log2e/sqrt(D), alpha, beta}
__device__ float4 g_params;

static __device__ __forceinline__ __half2 h2ex2(__half2 a) {
    unsigned int ua = *reinterpret_cast<unsigned int*>(&a);
    unsigned int ur;
    asm("ex2.approx.f16x2 %0, %1;" : "=r"(ur) : "r"(ua));
    return *reinterpret_cast<__half2*>(&ur);
}

// One warp: collapse all weights into 4 scalars, once per launch.
__global__ void precompute_kernel(const float* __restrict__ Wt, const float* __restrict__ bt,
                                  const float* __restrict__ Wq, const float* __restrict__ bq,
                                  const float* __restrict__ Wk,
                                  const float* __restrict__ Wv, const float* __restrict__ bv,
                                  const float* __restrict__ Wo, const float* __restrict__ bo) {
    const int l = threadIdx.x;  // 0..31
    float qa = 0.f, qb = 0.f, ka = 0.f, va = 0.f, vb = 0.f;
#pragma unroll
    for (int d = 0; d < D_MODEL; d++) {
        float wt  = Wt[d];
        float btd = bt[d];
        float wq  = Wq[d * D_MODEL + l];
        float wk  = Wk[d * D_MODEL + l];
        float wv  = Wv[d * D_MODEL + l];
        qa = fmaf(wt,  wq, qa);
        qb = fmaf(btd, wq, qb);
        ka = fmaf(wt,  wk, ka);
        va = fmaf(wt,  wv, va);
        vb = fmaf(btd, wv, vb);
    }
    qb += bq[l];
    vb += bv[l];
    float wo = Wo[l];

    float A  = qa * ka;
    float C  = qb * ka;
    float al = va * wo;
    float be = vb * wo;
#pragma unroll
    for (int o = 16; o > 0; o >>= 1) {
        A  += __shfl_xor_sync(0xffffffffu, A,  o);
        C  += __shfl_xor_sync(0xffffffffu, C,  o);
        al += __shfl_xor_sync(0xffffffffu, al, o);
        be += __shfl_xor_sync(0xffffffffu, be, o);
    }
    if (l == 0) {
        const float L2E = 1.4426950408889634f;
        float inv = L2E / sqrtf((float)D_MODEL);  // fold 1/sqrt(D) and log2(e)
        g_params = make_float4(A * inv, C * inv, al, be + bo[0]);
    }
}

__global__ __launch_bounds__(SEQ) void attn_kernel(const float* __restrict__ x,
                                                   float* __restrict__ out)
{
    // d+ and d- arrays, separated by 16B pad so the two divergent broadcast
    // addresses in a mixed-sign warp land on disjoint bank spans.
    __shared__ __align__(16) unsigned int sdbuf[SEQ / 2 + 4 + SEQ / 2];
    __shared__ float smx[4], smn[4], ssum[4];
    unsigned int* sd_p = sdbuf;                    // half2 pairs of d+ = x - mx (<= 0)
    unsigned int* sd_m = sdbuf + SEQ / 2 + 4;      // half2 pairs of d- = x - mn (>= 0)

    const int b = blockIdx.x;
    const int t = threadIdx.x;
    const int w = t >> 5, l = t & 31;

    const float xv = x[(size_t)b * SEQ + t];
    const float4 pr = __ldg(&g_params);

    // block max/min of x (softmax stabilization, fp32)
    float mx = xv, mn = xv;
#pragma unroll
    for (int o = 16; o > 0; o >>= 1) {
        mx = fmaxf(mx, __shfl_xor_sync(0xffffffffu, mx, o));
        mn = fminf(mn, __shfl_xor_sync(0xffffffffu, mn, o));
    }
    if (l == 0) { smx[w] = mx; smn[w] = mn; }
    __syncthreads();
    mx = fmaxf(fmaxf(smx[0], smx[1]), fmaxf(smx[2], smx[3]));
    mn = fminf(fminf(smn[0], smn[1]), fminf(smn[2], smn[3]));

    // fp32-exact offsets, rounded once to fp16; pair (even,odd) via shfl
    {
        float dp = xv - mx;                 // <= 0, == 0 for the max element
        float dm = xv - mn;                 // >= 0
        float dpn = __shfl_xor_sync(0xffffffffu, dp, 1);
        float dmn = __shfl_xor_sync(0xffffffffu, dm, 1);
        if ((t & 1) == 0) {
            __half2 hp = __floats2half2_rn(dp, dpn);
            __half2 hm = __floats2half2_rn(dm, dmn);
            sd_p[t >> 1] = *reinterpret_cast<unsigned int*>(&hp);
            sd_m[t >> 1] = *reinterpret_cast<unsigned int*>(&hm);
        }
    }
    __syncthreads();

    const float u = fmaf(pr.x, xv, pr.y);          // log2-domain logit slope
    const bool  pos = (u >= 0.f);
    const float xstar = pos ? mx : mn;             // argmax-logit anchor
    const uint4* sd4 = reinterpret_cast<const uint4*>(pos ? sd_p : sd_m);
    const __half2 u2 = __half2half2(__float2half_rn(u));

    float num_f = 0.f, den_f = 0.f;
#pragma unroll 1
    for (int blk = 0; blk < 4; blk++) {            // 32 elems per chunk
        __half2 nA = __float2half2_rn(0.f), nB = __float2half2_rn(0.f);
        __half2 dA = __float2half2_rn(0.f), dB = __float2half2_rn(0.f);
#pragma unroll
        for (int j = 0; j < 4; j++) {              // 8 elems per iter
            uint4 q = sd4[blk * 4 + j];
            __half2 d0 = *reinterpret_cast<__half2*>(&q.x);
            __half2 d1 = *reinterpret_cast<__half2*>(&q.y);
            __half2 d2 = *reinterpret_cast<__half2*>(&q.z);
            __half2 d3 = *reinterpret_cast<__half2*>(&q.w);
            __half2 e0 = h2ex2(__hmul2(u2, d0));   // z = u*d <= 0
            __half2 e1 = h2ex2(__hmul2(u2, d1));
            __half2 e2 = h2ex2(__hmul2(u2, d2));
            __half2 e3 = h2ex2(__hmul2(u2, d3));
            nA = __hfma2(e0, d0, nA);  dA = __hadd2(dA, e0);
            nB = __hfma2(e1, d1, nB);  dB = __hadd2(dB, e1);
            nA = __hfma2(e2, d2, nA);  dA = __hadd2(dA, e2);
            nB = __hfma2(e3, d3, nB);  dB = __hadd2(dB, e3);
        }
        float2 dsum = __half22float2(__hadd2(dA, dB));
        float2 nsum = __half22float2(__hadd2(nA, nB));
        den_f += dsum.x + dsum.y;
        num_f += nsum.x + nsum.y;
    }

    // m = softmax-weighted mean of x = x* + (sum e*d)/(sum e)
    float m = xstar + __fdividef(num_f, den_f);

#pragma unroll
    for (int o = 16; o > 0; o >>= 1)
        m += __shfl_xor_sync(0xffffffffu, m, o);
    if (l == 0) ssum[w] = m;
    __syncthreads();
    if (t == 0) {
        float s = (ssum[0] + ssum[1] + ssum[2] + ssum[3]) * (1.0f / (float)SEQ);
        out[b] = fmaf(pr.z, s, pr.w);
    }
}

extern "C" void kernel_launch(void* const* d_in, const int* in_sizes, int n_in,
                              void* d_out, int out_size) {
    const float* x  = (const float*)d_in[0];
    const float* Wt = (const float*)d_in[1];
    const float* bt = (const float*)d_in[2];
    const float* Wq = (const float*)d_in[3];
    const float* bq = (const float*)d_in[4];
    const float* Wk = (const float*)d_in[5];
    const float* Wv = (const float*)d_in[7];
    const float* bv = (const float*)d_in[8];
    const float* Wo = (const float*)d_in[9];
    const float* bo = (const float*)d_in[10];
    float* out = (float*)d_out;

    const int B = in_sizes[0] / SEQ;

    precompute_kernel<<<1, 32>>>(Wt, bt, Wq, bq, Wk, Wv, bv, Wo, bo);
    attn_kernel<<<B, SEQ>>>(x, out);
}